// round 1
// baseline (speedup 1.0000x reference)
#include <cuda_runtime.h>
#include <math.h>

#define B_    512
#define L_    37500
#define T_    74
#define NP_   1000
#define STEP_ 500
#define NF_   501
#define NMEL_ 64

// ---------------- scratch (device globals; no allocation) ----------------
__device__ float g_env[B_ * NF_];       // env[b][f] = mean over t of spec
__device__ float g_psumS[B_ * 32];      // per-b partial sums, spectral branch
__device__ float g_psumC[B_ * 24];      // per-b partial sums, cardiac branch
__device__ float g_meanS[32], g_meanC[24];
__device__ float g_aS[32], g_cS[32], g_aC[24], g_cC[24];
__device__ int   g_centers[NMEL_];

// ---------------- mel centers (fp64, matches numpy int(f/fr)) ----------------
__global__ void k_init() {
    int m = threadIdx.x;
    if (m >= NMEL_) return;
    if (m == 63) { g_centers[63] = -1; return; }  // pts has only 63 entries -> row 63 of M is zero
    double f;
    if (m < 21)       f = 0.1 + 0.4 * (double)m / 20.0;          // linspace(0.1,0.5,21)
    else if (m < 31)  f = 0.5 + 0.3 * (double)(m - 21) / 9.0;    // linspace(0.5,0.8,10)
    else              f = 0.8 + 2.2 * (double)(m - 31) / 31.0;   // linspace(0.8,3.0,32)
    double fr = 125.0 / 2.0 / (double)NF_;
    g_centers[m] = (int)(f / fr);
}

// ---------------- spectrogram: one block per (b, t) frame ----------------
// 1000-pt real DFT factored as 1000 = 40 x 25:
//   n = 25p + q (p<40, q<25);  X[k] = sum_q e^{-2pi i qk/1000} * Y[q, k mod 40]
//   Y[q,r] = sum_p x[25p+q] e^{-2pi i pr/40}; real input -> Y[q,40-r] = conj(Y[q,r])
__global__ void __launch_bounds__(128) k_spec(const float* __restrict__ x,
                                              float* __restrict__ spec) {
    const int bid = blockIdx.x;
    const int b = bid / T_, t = bid % T_;
    const float* xin = x + (size_t)b * L_ + (size_t)t * STEP_;

    __shared__ float xw[NP_];
    __shared__ float Yr[25][21];
    __shared__ float Yi[25][21];
    __shared__ float red[4];

    const int tid = threadIdx.x;

    // load frame + block-sum for detrend mean
    float v[8];
    float s = 0.f;
#pragma unroll
    for (int i = 0; i < 8; ++i) {
        int idx = tid + i * 128;
        float vv = 0.f;
        if (i < 7 || tid < 104) vv = xin[idx];
        v[i] = vv; s += vv;
    }
#pragma unroll
    for (int o = 16; o; o >>= 1) s += __shfl_down_sync(0xffffffffu, s, o);
    if ((tid & 31) == 0) red[tid >> 5] = s;
    __syncthreads();
    if (tid == 0) red[0] = (red[0] + red[1] + red[2] + red[3]) * (1.f / 1000.f);
    __syncthreads();
    const float mean = red[0];

    // detrend + Hann window
#pragma unroll
    for (int i = 0; i < 8; ++i) {
        int idx = tid + i * 128;
        if (i < 7 || tid < 104) {
            float win = 0.5f - 0.5f * cosf((float)idx * 6.2831853e-3f);
            xw[idx] = (v[i] - mean) * win;
        }
    }
    __syncthreads();

    // ---- stage 1: Y[q][r], r = 0..20, threads (r, qchunk of 5) ----
    if (tid < 105) {
        const int r  = tid % 21;
        const int q0 = (tid / 21) * 5;
        float cr, ci;
        {
            float sv, cv;
            sincosf((float)r * 0.15707963267948966f, &sv, &cv);  // 2*pi/40
            cr = cv; ci = -sv;
        }
        float ar0=0,ar1=0,ar2=0,ar3=0,ar4=0;
        float ai0=0,ai1=0,ai2=0,ai3=0,ai4=0;
        float wr = 1.f, wi = 0.f;
#pragma unroll 8
        for (int p = 0; p < 40; ++p) {
            const float* xp = &xw[25 * p + q0];
            float x0 = xp[0], x1 = xp[1], x2 = xp[2], x3 = xp[3], x4 = xp[4];
            ar0 += x0 * wr; ai0 += x0 * wi;
            ar1 += x1 * wr; ai1 += x1 * wi;
            ar2 += x2 * wr; ai2 += x2 * wi;
            ar3 += x3 * wr; ai3 += x3 * wi;
            ar4 += x4 * wr; ai4 += x4 * wi;
            float nwr = wr * cr - wi * ci;
            float nwi = wr * ci + wi * cr;
            wr = nwr; wi = nwi;
        }
        Yr[q0+0][r] = ar0; Yi[q0+0][r] = ai0;
        Yr[q0+1][r] = ar1; Yi[q0+1][r] = ai1;
        Yr[q0+2][r] = ar2; Yi[q0+2][r] = ai2;
        Yr[q0+3][r] = ar3; Yi[q0+3][r] = ai3;
        Yr[q0+4][r] = ar4; Yi[q0+4][r] = ai4;
    }
    __syncthreads();

    // ---- stage 2: X[k], k = 0..500 ----
    for (int k = tid; k < NF_; k += 128) {
        int r = k % 40;
        int rp; float sg;
        if (r <= 20) { rp = r;      sg =  1.f; }
        else         { rp = 40 - r; sg = -1.f; }
        float cr, ci;
        {
            float sv, cv;
            sincosf((float)k * 0.006283185307179586f, &sv, &cv);  // 2*pi/1000
            cr = cv; ci = -sv;
        }
        float wr = 1.f, wi = 0.f, Xr = 0.f, Xi = 0.f;
#pragma unroll 5
        for (int q = 0; q < 25; ++q) {
            float yr = Yr[q][rp];
            float yi = sg * Yi[q][rp];
            Xr += yr * wr - yi * wi;
            Xi += yr * wi + yi * wr;
            float nwr = wr * cr - wi * ci;
            float nwi = wr * ci + wi * cr;
            wr = nwr; wi = nwi;
        }
        // psd scale: /(fs * sum(win^2)) = /(125*375) = /46875, x2 for interior bins
        float sc  = (k == 0 || k == 500) ? (1.f / 46875.f) : (2.f / 46875.f);
        float psd = (Xr * Xr + Xi * Xi) * sc;
        spec[((size_t)b * NF_ + k) * T_ + t] = logf(psd + 1e-8f);
    }
}

// ---------------- env[b][f] = mean over t: one warp per row ----------------
__global__ void __launch_bounds__(256) k_env(const float* __restrict__ spec) {
    int gw   = (blockIdx.x * blockDim.x + threadIdx.x) >> 5;
    int lane = threadIdx.x & 31;
    if (gw >= B_ * NF_) return;
    const float* row = spec + (size_t)gw * T_;
    float s = 0.f;
    for (int i = lane; i < T_; i += 32) s += row[i];
#pragma unroll
    for (int o = 16; o; o >>= 1) s += __shfl_down_sync(0xffffffffu, s, o);
    if (lane == 0) g_env[gw] = s * (1.f / (float)T_);
}

// ---------------- mel gather ----------------
__global__ void __launch_bounds__(256) k_mel(const float* __restrict__ spec,
                                             float* __restrict__ mel) {
    int i = blockIdx.x * blockDim.x + threadIdx.x;
    if (i >= B_ * NMEL_ * T_) return;
    int t = i % T_;
    int m = (i / T_) % NMEL_;
    int b = i / (T_ * NMEL_);
    int c = g_centers[m];
    float vv = 0.f;
    if (c >= 0) vv = spec[((size_t)b * NF_ + c) * T_ + t];
    mel[i] = vv;
}

// ---------------- BN pass helpers: conv sums (pass=0) / var sums (pass=1) ----------------
template<int PASS>
__global__ void __launch_bounds__(256) k_bnstats(const float* __restrict__ w5, const float* __restrict__ b5,
                                                 const float* __restrict__ w7, const float* __restrict__ b7) {
    const int b = blockIdx.x, tid = threadIdx.x;
    __shared__ float e[NF_ + 4];   // env padded by 2 each side (zeros)
    __shared__ float cp[24];       // cprof (18) padded by 3 each side (zeros)
    for (int i = tid; i < NF_ + 4; i += 256) {
        int f = i - 2;
        e[i] = (f >= 0 && f < NF_) ? g_env[b * NF_ + f] : 0.f;
    }
    if (tid < 24) {
        int j = tid - 3;
        cp[tid] = (j >= 0 && j < 18) ? g_env[b * NF_ + 6 + j] : 0.f;
    }
    __syncthreads();

    // spectral branch: 32 channels x 8 lanes each over l
    {
        const int o = tid >> 3, sub = tid & 7;
        float wv[5];
#pragma unroll
        for (int k = 0; k < 5; ++k) wv[k] = w5[o * 5 + k];
        const float bb = b5[o];
        const float m  = PASS ? g_meanS[o] : 0.f;
        float acc = 0.f;
        for (int l = sub; l < NF_; l += 8) {
            float y = bb;
#pragma unroll
            for (int k = 0; k < 5; ++k) y += wv[k] * e[l + k];
            if (PASS) { float d = y - m; acc += d * d; } else acc += y;
        }
#pragma unroll
        for (int d = 4; d; d >>= 1) acc += __shfl_down_sync(0xffffffffu, acc, d, 8);
        if (sub == 0) g_psumS[b * 32 + o] = acc;
    }
    // cardiac branch: 24 channels, serial over l (tiny)
    if (tid < 24) {
        const int oc = tid;
        const float m = PASS ? g_meanC[oc] : 0.f;
        float acc = 0.f;
        for (int l = 0; l < 18; ++l) {
            float y = b7[oc];
#pragma unroll
            for (int k = 0; k < 7; ++k) y += w7[oc * 7 + k] * cp[l + k];
            if (PASS) { float d = y - m; acc += d * d; } else acc += y;
        }
        g_psumC[b * 24 + oc] = acc;
    }
}

__global__ void k_reduce_mean() {
    int t = threadIdx.x;
    if (t < 32) {
        float s = 0.f;
        for (int b = 0; b < B_; ++b) s += g_psumS[b * 32 + t];
        g_meanS[t] = s / (float)(B_ * NF_);
    } else if (t < 56) {
        int o = t - 32; float s = 0.f;
        for (int b = 0; b < B_; ++b) s += g_psumC[b * 24 + o];
        g_meanC[o] = s / (float)(B_ * 18);
    }
}

__global__ void k_reduce_var(const float* __restrict__ gS, const float* __restrict__ btS,
                             const float* __restrict__ gC, const float* __restrict__ btC) {
    int t = threadIdx.x;
    if (t < 32) {
        float s = 0.f;
        for (int b = 0; b < B_; ++b) s += g_psumS[b * 32 + t];
        float var = s / (float)(B_ * NF_);
        float a = gS[t] * rsqrtf(var + 1e-5f);
        g_aS[t] = a; g_cS[t] = btS[t] - g_meanS[t] * a;
    } else if (t < 56) {
        int o = t - 32; float s = 0.f;
        for (int b = 0; b < B_; ++b) s += g_psumC[b * 24 + o];
        float var = s / (float)(B_ * 18);
        float a = gC[o] * rsqrtf(var + 1e-5f);
        g_aC[o] = a; g_cC[o] = btC[o] - g_meanC[o] * a;
    }
}

// ---------------- finalize: spectral out, cfeat, rfeat ----------------
__global__ void __launch_bounds__(256) k_final(const float* __restrict__ w5, const float* __restrict__ b5,
                                               const float* __restrict__ w7, const float* __restrict__ b7,
                                               const float* __restrict__ w1, const float* __restrict__ b1,
                                               const float* __restrict__ w2, const float* __restrict__ b2,
                                               float* __restrict__ outSpectral,
                                               float* __restrict__ outR,
                                               float* __restrict__ outC) {
    const int b = blockIdx.x, tid = threadIdx.x;
    __shared__ float e[NF_ + 4];
    __shared__ float cp[24];
    __shared__ float ws5[160], bs5[32], aSs[32], cSs[32];
    __shared__ float rpp[9];        // rprof padded (len 5 data, pad 2 each side)
    __shared__ float r1p[16][7];    // relu(conv1) padded by 1 each side

    for (int i = tid; i < NF_ + 4; i += 256) {
        int f = i - 2;
        e[i] = (f >= 0 && f < NF_) ? g_env[b * NF_ + f] : 0.f;
    }
    if (tid < 24) {
        int j = tid - 3;
        cp[tid] = (j >= 0 && j < 18) ? g_env[b * NF_ + 6 + j] : 0.f;
    }
    if (tid < 160) ws5[tid] = w5[tid];
    if (tid < 32) { bs5[tid] = b5[tid]; aSs[tid] = g_aS[tid]; cSs[tid] = g_cS[tid]; }
    if (tid < 9) {  // rprof = env[:, 0:4] padded to 5 (last = 0), then conv pad 2
        int j = tid - 2;
        rpp[tid] = (j >= 0 && j < 4) ? g_env[b * NF_ + j] : 0.f;
    }
    if (tid < 16) { r1p[tid][0] = 0.f; r1p[tid][6] = 0.f; }
    __syncthreads();

    // resp conv1 + relu
    if (tid < 80) {
        int i = tid / 5, l = tid % 5;
        float y = b1[i];
#pragma unroll
        for (int k = 0; k < 5; ++k) y += w1[i * 5 + k] * rpp[l + k];
        r1p[i][l + 1] = fmaxf(0.f, y);
    }

    // spectral output (coalesced in l)
    for (int idx = tid; idx < 32 * NF_; idx += 256) {
        int o = idx / NF_, l = idx - o * NF_;
        float y = bs5[o];
#pragma unroll
        for (int k = 0; k < 5; ++k) y += ws5[o * 5 + k] * e[l + k];
        outSpectral[(size_t)b * 32 * NF_ + idx] = fmaxf(0.f, y * aSs[o] + cSs[o]);
    }

    // cfeat (mean over 18, pad channels 24..31 with zeros)
    if (tid < 32) {
        float val = 0.f;
        if (tid < 24) {
            const int oc = tid;
            const float a = g_aC[oc], c = g_cC[oc];
            float acc = 0.f;
            for (int l = 0; l < 18; ++l) {
                float y = b7[oc];
#pragma unroll
                for (int k = 0; k < 7; ++k) y += w7[oc * 7 + k] * cp[l + k];
                acc += fmaxf(0.f, y * a + c);
            }
            val = acc / 18.f;
        }
        outC[b * 32 + tid] = val;
    }
    __syncthreads();

    // resp conv2 + mean over 5
    if (tid < 32) {
        const int o = tid;
        float acc = 5.f * b2[o];
        for (int i = 0; i < 16; ++i) {
#pragma unroll
            for (int l = 0; l < 5; ++l)
#pragma unroll
                for (int k = 0; k < 3; ++k)
                    acc += w2[o * 48 + i * 3 + k] * r1p[i][l + k];
        }
        outR[b * 32 + o] = acc * 0.2f;
    }
}

// ---------------- launch ----------------
extern "C" void kernel_launch(void* const* d_in, const int* in_sizes, int n_in,
                              void* d_out, int out_size) {
    (void)in_sizes; (void)n_in; (void)out_size;
    const float* x   = (const float*)d_in[0];
    const float* w5  = (const float*)d_in[1];
    const float* b5  = (const float*)d_in[2];
    const float* g5  = (const float*)d_in[3];
    const float* bt5 = (const float*)d_in[4];
    const float* w7  = (const float*)d_in[5];
    const float* b7  = (const float*)d_in[6];
    const float* g7  = (const float*)d_in[7];
    const float* bt7 = (const float*)d_in[8];
    const float* w1  = (const float*)d_in[9];
    const float* b1  = (const float*)d_in[10];
    const float* w2  = (const float*)d_in[11];
    const float* b2  = (const float*)d_in[12];

    float* out         = (float*)d_out;
    float* outMel      = out;                                   // (512,64,74)
    float* outSpectral = outMel + (size_t)B_ * 64 * T_;         // (512,32,501)
    float* outR        = outSpectral + (size_t)B_ * 32 * NF_;   // (512,32)
    float* outC        = outR + (size_t)B_ * 32;                // (512,32)
    float* outSpec     = outC + (size_t)B_ * 32;                // (512,501,74)

    k_init<<<1, 64>>>();
    k_spec<<<B_ * T_, 128>>>(x, outSpec);
    k_env<<<(B_ * NF_) / 8, 256>>>(outSpec);
    k_mel<<<(B_ * NMEL_ * T_ + 255) / 256, 256>>>(outSpec, outMel);
    k_bnstats<0><<<B_, 256>>>(w5, b5, w7, b7);
    k_reduce_mean<<<1, 64>>>();
    k_bnstats<1><<<B_, 256>>>(w5, b5, w7, b7);
    k_reduce_var<<<1, 64>>>(g5, bt5, g7, bt7);
    k_final<<<B_, 256>>>(w5, b5, w7, b7, w1, b1, w2, b2, outSpectral, outR, outC);
}

// round 2
// speedup vs baseline: 1.7058x; 1.7058x over previous
#include <cuda_runtime.h>
#include <math.h>

#define B_    512
#define L_    37500
#define T_    74
#define STEP_ 500
#define NF_   501
#define NMEL_ 64
#define KP_   504   // padded k-pitch for scratch

// ---------------- scratch (device globals; no allocation) ----------------
__device__ float g_tmp[(size_t)B_ * T_ * KP_];   // log-PSD in [b][t][k] layout (coalesced writes)
__device__ float g_env[B_ * NF_];
__device__ float g_psumS[B_ * 32];
__device__ float g_psumC[B_ * 24];
__device__ float g_meanS[32], g_meanC[24];
__device__ float g_aS[32], g_cS[32], g_aC[24], g_cC[24];
__device__ int   g_centers[NMEL_];

// ---------------- mel centers (fp64, matches numpy int(f/fr)) ----------------
__global__ void k_init() {
    int m = threadIdx.x;
    if (m >= NMEL_) return;
    if (m == 63) { g_centers[63] = -1; return; }  // pts has only 63 entries -> row 63 zero
    double f;
    if (m < 21)       f = 0.1 + 0.4 * (double)m / 20.0;
    else if (m < 31)  f = 0.5 + 0.3 * (double)(m - 21) / 9.0;
    else              f = 0.8 + 2.2 * (double)(m - 31) / 31.0;
    double fr = 125.0 / 2.0 / (double)NF_;
    g_centers[m] = (int)(f / fr);
}

// ---------------- spectrogram: one block per (b, t) frame ----------------
// 1000-pt real DFT, 4-stage factorization: n = 125u + 25v + q, q = 5a + b5
//   Stage A: Z[j][25v+q] = sum_u xw[125u+25v+q] e^{-2pi i u j/8}   (real 8-pt DFT, j=0..4 + conj)
//   Stage B: Y[r][q]     = sum_v Z[r mod 8][25v+q] e^{-2pi i v r/40}, r=0..20 (conj for 21..39)
//   Stage C1: W[b5][r+40s] = DFT5_s( Y[5a+b5][r] * e^{-2pi i a r/200} )
//   Stage C2: X[m+200c]    = DFT5_c( W[b5][m]    * e^{-2pi i b5 m/1000} ), c=0..2
__global__ void __launch_bounds__(128) k_spec(const float* __restrict__ x) {
    const int bid = blockIdx.x;
    const int b = bid / T_, t = bid % T_;
    const float* xin = x + (size_t)b * L_ + (size_t)t * STEP_;

    __shared__ float xw[1000];
    __shared__ float Zr[5][125], Zi[5][125];
    __shared__ float Yr[21][25], Yi[21][25];
    __shared__ float Wsr[5][200], Wsi[5][200];
    __shared__ float red[4];

    const int tid = threadIdx.x;

    // ---- load frame + detrend mean ----
    float v[8];
    float s = 0.f;
#pragma unroll
    for (int i = 0; i < 8; ++i) {
        int idx = tid + i * 128;
        float vv = 0.f;
        if (i < 7 || tid < 104) vv = xin[idx];
        v[i] = vv; s += vv;
    }
#pragma unroll
    for (int o = 16; o; o >>= 1) s += __shfl_down_sync(0xffffffffu, s, o);
    if ((tid & 31) == 0) red[tid >> 5] = s;
    __syncthreads();
    if (tid == 0) red[0] = (red[0] + red[1] + red[2] + red[3]) * (1.f / 1000.f);
    __syncthreads();
    const float mean = red[0];

    // ---- detrend + Hann window ----
#pragma unroll
    for (int i = 0; i < 8; ++i) {
        int idx = tid + i * 128;
        if (i < 7 || tid < 104) {
            float win = 0.5f - 0.5f * cosf((float)idx * 6.2831853071795865e-3f);
            xw[idx] = (v[i] - mean) * win;
        }
    }
    __syncthreads();

    // ---- Stage A: 125 real 8-point DFTs (thread tid = 25v + q) ----
    if (tid < 125) {
        float e0 = xw[tid],       e1 = xw[125 + tid], e2 = xw[250 + tid], e3 = xw[375 + tid];
        float e4 = xw[500 + tid], e5 = xw[625 + tid], e6 = xw[750 + tid], e7 = xw[875 + tid];
        float a0 = e0 + e4, a1 = e1 + e5, a2 = e2 + e6, a3 = e3 + e7;
        float b0 = e0 - e4, b1 = e1 - e5, b2 = e2 - e6, b3 = e3 - e7;
        float s1 = a0 + a2, s2 = a1 + a3;
        const float RC = 0.70710678118654752f;
        float t1c = RC * (b1 - b3);
        float t2c = RC * (b1 + b3);
        Zr[0][tid] = s1 + s2;      Zi[0][tid] = 0.f;
        Zr[1][tid] = b0 + t1c;     Zi[1][tid] = -(t2c + b2);
        Zr[2][tid] = a0 - a2;      Zi[2][tid] = -(a1 - a3);
        Zr[3][tid] = b0 - t1c;     Zi[3][tid] = b2 - t2c;
        Zr[4][tid] = s1 - s2;      Zi[4][tid] = 0.f;
    }
    __syncthreads();

    // ---- Stage B: Y[r][q], r = 0..20; threads (r, 5-q chunk) ----
    if (tid < 105) {
        const int r  = tid % 21;
        const int q0 = (tid / 21) * 5;
        float sv, cv;
        sincosf((float)r * 0.15707963267948966f, &sv, &cv);   // 2*pi/40
        float w1r = cv,  w1i = -sv;
        float w2r = w1r * w1r - w1i * w1i, w2i = 2.f * w1r * w1i;
        float w3r = w2r * w1r - w2i * w1i, w3i = w2r * w1i + w2i * w1r;
        float w4r = w2r * w2r - w2i * w2i, w4i = 2.f * w2r * w2i;
        int j = r & 7;
        int jj; float zsg;
        if (j <= 4) { jj = j;     zsg =  1.f; }
        else        { jj = 8 - j; zsg = -1.f; }
#pragma unroll
        for (int dq = 0; dq < 5; ++dq) {
            int q = q0 + dq;
            float z0r = Zr[jj][q],        z0i = zsg * Zi[jj][q];
            float z1r = Zr[jj][25 + q],   z1i = zsg * Zi[jj][25 + q];
            float z2r = Zr[jj][50 + q],   z2i = zsg * Zi[jj][50 + q];
            float z3r = Zr[jj][75 + q],   z3i = zsg * Zi[jj][75 + q];
            float z4r = Zr[jj][100 + q],  z4i = zsg * Zi[jj][100 + q];
            float ar = z0r, ai = z0i;
            ar += w1r * z1r - w1i * z1i;  ai += w1r * z1i + w1i * z1r;
            ar += w2r * z2r - w2i * z2i;  ai += w2r * z2i + w2i * z2r;
            ar += w3r * z3r - w3i * z3i;  ai += w3r * z3i + w3i * z3r;
            ar += w4r * z4r - w4i * z4i;  ai += w4r * z4i + w4i * z4r;
            Yr[r][q] = ar; Yi[r][q] = ai;
        }
    }
    __syncthreads();

    const float C1 = 0.30901699437494745f, C2 = -0.80901699437494745f;
    const float S1 = 0.95105651629515357f, S2 =  0.58778525229247313f;

    // ---- Stage C1: radix-5 over a; items (b5, r), r = 0..39 ----
    for (int it = tid; it < 200; it += 128) {
        const int b5 = it / 40, r = it % 40;
        int rr; float ysg;
        if (r <= 20) { rr = r;      ysg =  1.f; }
        else         { rr = 40 - r; ysg = -1.f; }
        float sv, cv;
        sincosf((float)r * 0.031415926535897934f, &sv, &cv);  // 2*pi/200
        float w1r = cv,  w1i = -sv;
        float w2r = w1r * w1r - w1i * w1i, w2i = 2.f * w1r * w1i;
        float w3r = w2r * w1r - w2i * w1i, w3i = w2r * w1i + w2i * w1r;
        float w4r = w2r * w2r - w2i * w2i, w4i = 2.f * w2r * w2i;

        float y0r = Yr[rr][b5],       y0i = ysg * Yi[rr][b5];
        float p1r = Yr[rr][5  + b5],  p1i = ysg * Yi[rr][5  + b5];
        float p2r = Yr[rr][10 + b5],  p2i = ysg * Yi[rr][10 + b5];
        float p3r = Yr[rr][15 + b5],  p3i = ysg * Yi[rr][15 + b5];
        float p4r = Yr[rr][20 + b5],  p4i = ysg * Yi[rr][20 + b5];

        float y1r = w1r * p1r - w1i * p1i, y1i = w1r * p1i + w1i * p1r;
        float y2r = w2r * p2r - w2i * p2i, y2i = w2r * p2i + w2i * p2r;
        float y3r = w3r * p3r - w3i * p3i, y3i = w3r * p3i + w3i * p3r;
        float y4r = w4r * p4r - w4i * p4i, y4i = w4r * p4i + w4i * p4r;

        float t1r = y1r + y4r, t1i = y1i + y4i;
        float t2r = y2r + y3r, t2i = y2i + y3i;
        float t3r = y1r - y4r, t3i = y1i - y4i;
        float t4r = y2r - y3r, t4i = y2i - y3i;
        float Ar = C1 * t1r + C2 * t2r, Ai = C1 * t1i + C2 * t2i;
        float Br = C2 * t1r + C1 * t2r, Bi = C2 * t1i + C1 * t2i;
        float Cr = S1 * t3r + S2 * t4r, Ci = S1 * t3i + S2 * t4i;
        float Dr = S2 * t3r - S1 * t4r, Di = S2 * t3i - S1 * t4i;

        Wsr[b5][r]       = y0r + t1r + t2r;  Wsi[b5][r]       = y0i + t1i + t2i;
        Wsr[b5][r + 40]  = y0r + Ar + Ci;    Wsi[b5][r + 40]  = y0i + Ai - Cr;
        Wsr[b5][r + 80]  = y0r + Br + Di;    Wsi[b5][r + 80]  = y0i + Bi - Dr;
        Wsr[b5][r + 120] = y0r + Br - Di;    Wsi[b5][r + 120] = y0i + Bi + Dr;
        Wsr[b5][r + 160] = y0r + Ar - Ci;    Wsi[b5][r + 160] = y0i + Ai + Cr;
    }
    __syncthreads();

    // ---- Stage C2: twiddle + partial DFT-5 (c = 0,1,2) + psd/log ----
    float* outrow = g_tmp + ((size_t)b * T_ + t) * KP_;
    const float SC2 = 2.f / 46875.f;  // fs * sum(win^2) = 125 * 375
    for (int m = tid; m < 200; m += 128) {
        float sv, cv;
        sincosf((float)m * 0.0062831853071795865f, &sv, &cv);  // 2*pi/1000
        float w1r = cv,  w1i = -sv;
        float w2r = w1r * w1r - w1i * w1i, w2i = 2.f * w1r * w1i;
        float w3r = w2r * w1r - w2i * w1i, w3i = w2r * w1i + w2i * w1r;
        float w4r = w2r * w2r - w2i * w2i, w4i = 2.f * w2r * w2i;

        float z0r = Wsr[0][m],  z0i = Wsi[0][m];
        float p1r = Wsr[1][m],  p1i = Wsi[1][m];
        float p2r = Wsr[2][m],  p2i = Wsi[2][m];
        float p3r = Wsr[3][m],  p3i = Wsi[3][m];
        float p4r = Wsr[4][m],  p4i = Wsi[4][m];

        float z1r = w1r * p1r - w1i * p1i, z1i = w1r * p1i + w1i * p1r;
        float z2r = w2r * p2r - w2i * p2i, z2i = w2r * p2i + w2i * p2r;
        float z3r = w3r * p3r - w3i * p3i, z3i = w3r * p3i + w3i * p3r;
        float z4r = w4r * p4r - w4i * p4i, z4i = w4r * p4i + w4i * p4r;

        float t1r = z1r + z4r, t1i = z1i + z4i;
        float t2r = z2r + z3r, t2i = z2i + z3i;
        float t3r = z1r - z4r, t3i = z1i - z4i;
        float t4r = z2r - z3r, t4i = z2i - z3i;

        // c = 0 : k = m
        {
            float Xr = z0r + t1r + t2r, Xi = z0i + t1i + t2i;
            float sc = (m == 0) ? (1.f / 46875.f) : SC2;
            outrow[m] = logf((Xr * Xr + Xi * Xi) * sc + 1e-8f);
        }
        float Ar = C1 * t1r + C2 * t2r, Ai = C1 * t1i + C2 * t2i;
        float Cr = S1 * t3r + S2 * t4r, Ci = S1 * t3i + S2 * t4i;
        // c = 1 : k = m + 200
        {
            float Xr = z0r + Ar + Ci, Xi = z0i + Ai - Cr;
            outrow[m + 200] = logf((Xr * Xr + Xi * Xi) * SC2 + 1e-8f);
        }
        // c = 2 : k = m + 400 (only m <= 100)
        if (m <= 100) {
            float Br = C2 * t1r + C1 * t2r, Bi = C2 * t1i + C1 * t2i;
            float Dr = S2 * t3r - S1 * t4r, Di = S2 * t3i - S1 * t4i;
            float Xr = z0r + Br + Di, Xi = z0i + Bi - Dr;
            float sc = (m == 100) ? (1.f / 46875.f) : SC2;
            outrow[m + 400] = logf((Xr * Xr + Xi * Xi) * sc + 1e-8f);
        }
    }
}

// ---------------- transpose [b][t][k] -> spec[b][k][t], fused env reduction ----------------
__global__ void __launch_bounds__(256) k_transpose(float* __restrict__ spec) {
    const int bb = blockIdx.x >> 4;          // batch
    const int k0 = (blockIdx.x & 15) * 32;   // k-tile
    const int tid = threadIdx.x;
    __shared__ float tile[T_][33];

    for (int i = tid; i < T_ * 32; i += 256) {
        int tt = i >> 5, kx = i & 31;
        int k = k0 + kx;
        tile[tt][kx] = (k < NF_) ? g_tmp[((size_t)bb * T_ + tt) * KP_ + k] : 0.f;
    }
    __syncthreads();

    for (int i = tid; i < 32 * T_; i += 256) {
        int kx = i / T_, tt = i - kx * T_;
        int k = k0 + kx;
        if (k < NF_) spec[((size_t)bb * NF_ + k) * T_ + tt] = tile[tt][kx];
    }
    if (tid < 32) {
        int k = k0 + tid;
        if (k < NF_) {
            float s = 0.f;
            for (int tt = 0; tt < T_; ++tt) s += tile[tt][tid];
            g_env[bb * NF_ + k] = s * (1.f / (float)T_);
        }
    }
}

// ---------------- mel gather ----------------
__global__ void __launch_bounds__(256) k_mel(const float* __restrict__ spec,
                                             float* __restrict__ mel) {
    int i = blockIdx.x * blockDim.x + threadIdx.x;
    if (i >= B_ * NMEL_ * T_) return;
    int t = i % T_;
    int m = (i / T_) % NMEL_;
    int b = i / (T_ * NMEL_);
    int c = g_centers[m];
    float vv = 0.f;
    if (c >= 0) vv = spec[((size_t)b * NF_ + c) * T_ + t];
    mel[i] = vv;
}

// ---------------- BN stats: conv sums (PASS=0) / var sums (PASS=1) ----------------
template<int PASS>
__global__ void __launch_bounds__(256) k_bnstats(const float* __restrict__ w5, const float* __restrict__ b5,
                                                 const float* __restrict__ w7, const float* __restrict__ b7) {
    const int b = blockIdx.x, tid = threadIdx.x;
    __shared__ float e[NF_ + 4];
    __shared__ float cp[24];
    for (int i = tid; i < NF_ + 4; i += 256) {
        int f = i - 2;
        e[i] = (f >= 0 && f < NF_) ? g_env[b * NF_ + f] : 0.f;
    }
    if (tid < 24) {
        int j = tid - 3;
        cp[tid] = (j >= 0 && j < 18) ? g_env[b * NF_ + 6 + j] : 0.f;
    }
    __syncthreads();

    {
        const int o = tid >> 3, sub = tid & 7;
        float wv[5];
#pragma unroll
        for (int k = 0; k < 5; ++k) wv[k] = w5[o * 5 + k];
        const float bb = b5[o];
        const float m  = PASS ? g_meanS[o] : 0.f;
        float acc = 0.f;
        for (int l = sub; l < NF_; l += 8) {
            float y = bb;
#pragma unroll
            for (int k = 0; k < 5; ++k) y += wv[k] * e[l + k];
            if (PASS) { float d = y - m; acc += d * d; } else acc += y;
        }
#pragma unroll
        for (int d = 4; d; d >>= 1) acc += __shfl_down_sync(0xffffffffu, acc, d, 8);
        if (sub == 0) g_psumS[b * 32 + o] = acc;
    }
    if (tid < 24) {
        const int oc = tid;
        const float m = PASS ? g_meanC[oc] : 0.f;
        float acc = 0.f;
        for (int l = 0; l < 18; ++l) {
            float y = b7[oc];
#pragma unroll
            for (int k = 0; k < 7; ++k) y += w7[oc * 7 + k] * cp[l + k];
            if (PASS) { float d = y - m; acc += d * d; } else acc += y;
        }
        g_psumC[b * 24 + oc] = acc;
    }
}

__global__ void k_reduce_mean() {
    int t = threadIdx.x;
    if (t < 32) {
        float s = 0.f;
        for (int b = 0; b < B_; ++b) s += g_psumS[b * 32 + t];
        g_meanS[t] = s / (float)(B_ * NF_);
    } else if (t < 56) {
        int o = t - 32; float s = 0.f;
        for (int b = 0; b < B_; ++b) s += g_psumC[b * 24 + o];
        g_meanC[o] = s / (float)(B_ * 18);
    }
}

__global__ void k_reduce_var(const float* __restrict__ gS, const float* __restrict__ btS,
                             const float* __restrict__ gC, const float* __restrict__ btC) {
    int t = threadIdx.x;
    if (t < 32) {
        float s = 0.f;
        for (int b = 0; b < B_; ++b) s += g_psumS[b * 32 + t];
        float var = s / (float)(B_ * NF_);
        float a = gS[t] * rsqrtf(var + 1e-5f);
        g_aS[t] = a; g_cS[t] = btS[t] - g_meanS[t] * a;
    } else if (t < 56) {
        int o = t - 32; float s = 0.f;
        for (int b = 0; b < B_; ++b) s += g_psumC[b * 24 + o];
        float var = s / (float)(B_ * 18);
        float a = gC[o] * rsqrtf(var + 1e-5f);
        g_aC[o] = a; g_cC[o] = btC[o] - g_meanC[o] * a;
    }
}

// ---------------- finalize: spectral out, cfeat, rfeat ----------------
__global__ void __launch_bounds__(256) k_final(const float* __restrict__ w5, const float* __restrict__ b5,
                                               const float* __restrict__ w7, const float* __restrict__ b7,
                                               const float* __restrict__ w1, const float* __restrict__ b1,
                                               const float* __restrict__ w2, const float* __restrict__ b2,
                                               float* __restrict__ outSpectral,
                                               float* __restrict__ outR,
                                               float* __restrict__ outC) {
    const int b = blockIdx.x, tid = threadIdx.x;
    __shared__ float e[NF_ + 4];
    __shared__ float cp[24];
    __shared__ float ws5[160], bs5[32], aSs[32], cSs[32];
    __shared__ float rpp[9];
    __shared__ float r1p[16][7];

    for (int i = tid; i < NF_ + 4; i += 256) {
        int f = i - 2;
        e[i] = (f >= 0 && f < NF_) ? g_env[b * NF_ + f] : 0.f;
    }
    if (tid < 24) {
        int j = tid - 3;
        cp[tid] = (j >= 0 && j < 18) ? g_env[b * NF_ + 6 + j] : 0.f;
    }
    if (tid < 160) ws5[tid] = w5[tid];
    if (tid < 32) { bs5[tid] = b5[tid]; aSs[tid] = g_aS[tid]; cSs[tid] = g_cS[tid]; }
    if (tid < 9) {
        int j = tid - 2;
        rpp[tid] = (j >= 0 && j < 4) ? g_env[b * NF_ + j] : 0.f;
    }
    if (tid < 16) { r1p[tid][0] = 0.f; r1p[tid][6] = 0.f; }
    __syncthreads();

    if (tid < 80) {
        int i = tid / 5, l = tid % 5;
        float y = b1[i];
#pragma unroll
        for (int k = 0; k < 5; ++k) y += w1[i * 5 + k] * rpp[l + k];
        r1p[i][l + 1] = fmaxf(0.f, y);
    }

    for (int idx = tid; idx < 32 * NF_; idx += 256) {
        int o = idx / NF_, l = idx - o * NF_;
        float y = bs5[o];
#pragma unroll
        for (int k = 0; k < 5; ++k) y += ws5[o * 5 + k] * e[l + k];
        outSpectral[(size_t)b * 32 * NF_ + idx] = fmaxf(0.f, y * aSs[o] + cSs[o]);
    }

    if (tid < 32) {
        float val = 0.f;
        if (tid < 24) {
            const int oc = tid;
            const float a = g_aC[oc], c = g_cC[oc];
            float acc = 0.f;
            for (int l = 0; l < 18; ++l) {
                float y = b7[oc];
#pragma unroll
                for (int k = 0; k < 7; ++k) y += w7[oc * 7 + k] * cp[l + k];
                acc += fmaxf(0.f, y * a + c);
            }
            val = acc / 18.f;
        }
        outC[b * 32 + tid] = val;
    }
    __syncthreads();

    if (tid < 32) {
        const int o = tid;
        float acc = 5.f * b2[o];
        for (int i = 0; i < 16; ++i) {
#pragma unroll
            for (int l = 0; l < 5; ++l)
#pragma unroll
                for (int k = 0; k < 3; ++k)
                    acc += w2[o * 48 + i * 3 + k] * r1p[i][l + k];
        }
        outR[b * 32 + o] = acc * 0.2f;
    }
}

// ---------------- launch ----------------
extern "C" void kernel_launch(void* const* d_in, const int* in_sizes, int n_in,
                              void* d_out, int out_size) {
    (void)in_sizes; (void)n_in; (void)out_size;
    const float* x   = (const float*)d_in[0];
    const float* w5  = (const float*)d_in[1];
    const float* b5  = (const float*)d_in[2];
    const float* g5  = (const float*)d_in[3];
    const float* bt5 = (const float*)d_in[4];
    const float* w7  = (const float*)d_in[5];
    const float* b7  = (const float*)d_in[6];
    const float* g7  = (const float*)d_in[7];
    const float* bt7 = (const float*)d_in[8];
    const float* w1  = (const float*)d_in[9];
    const float* b1  = (const float*)d_in[10];
    const float* w2  = (const float*)d_in[11];
    const float* b2  = (const float*)d_in[12];

    float* out         = (float*)d_out;
    float* outMel      = out;
    float* outSpectral = outMel + (size_t)B_ * 64 * T_;
    float* outR        = outSpectral + (size_t)B_ * 32 * NF_;
    float* outC        = outR + (size_t)B_ * 32;
    float* outSpec     = outC + (size_t)B_ * 32;

    k_init<<<1, 64>>>();
    k_spec<<<B_ * T_, 128>>>(x);
    k_transpose<<<B_ * 16, 256>>>(outSpec);
    k_mel<<<(B_ * NMEL_ * T_ + 255) / 256, 256>>>(outSpec, outMel);
    k_bnstats<0><<<B_, 256>>>(w5, b5, w7, b7);
    k_reduce_mean<<<1, 64>>>();
    k_bnstats<1><<<B_, 256>>>(w5, b5, w7, b7);
    k_reduce_var<<<1, 64>>>(g5, bt5, g7, bt7);
    k_final<<<B_, 256>>>(w5, b5, w7, b7, w1, b1, w2, b2, outSpectral, outR, outC);
}

// round 3
// speedup vs baseline: 1.8012x; 1.0559x over previous
#include <cuda_runtime.h>
#include <math.h>

#define B_    512
#define L_    37500
#define T_    74
#define STEP_ 500
#define NF_   501
#define NMEL_ 64
#define KP_   504   // padded k-pitch for scratch

// ---------------- scratch (device globals; no allocation) ----------------
__device__ float g_tmp[(size_t)B_ * T_ * KP_];   // log-PSD in [b][t][k] layout
__device__ float g_env[B_ * NF_];
__device__ float g_psumS[B_ * 32];
__device__ float g_psumC[B_ * 24];
__device__ float g_meanS[32], g_meanC[24];
__device__ float g_aS[32], g_cS[32], g_aC[24], g_cC[24];
__device__ int   g_centers[NMEL_];
__device__ float g_win[1000];
__device__ float4 g_twB[21 * 2];    // e^{-2pi i k r/40},  k=1..4, packed (w1r,w1i,w2r,w2i),(w3r,w3i,w4r,w4i)
__device__ float4 g_twC1[40 * 2];   // e^{-2pi i k r/200}
__device__ float4 g_twC2[200 * 2];  // e^{-2pi i k m/1000}

// ---------------- init: mel centers, window, twiddle tables (fp64) ----------------
__global__ void k_init() {
    int i = blockIdx.x * blockDim.x + threadIdx.x;
    if (i < NMEL_) {
        if (i == 63) g_centers[63] = -1;   // pts has only 63 entries -> row 63 zero
        else {
            double f;
            if (i < 21)       f = 0.1 + 0.4 * (double)i / 20.0;
            else if (i < 31)  f = 0.5 + 0.3 * (double)(i - 21) / 9.0;
            else              f = 0.8 + 2.2 * (double)(i - 31) / 31.0;
            double fr = 125.0 / 2.0 / (double)NF_;
            g_centers[i] = (int)(f / fr);
        }
    }
    if (i < 1000)
        g_win[i] = (float)(0.5 - 0.5 * cos(6.283185307179586476925287 * (double)i / 1000.0));
    if (i < 21) {
        double th = -6.283185307179586476925287 * (double)i / 40.0;
        g_twB[2*i]   = make_float4((float)cos(th),   (float)sin(th),   (float)cos(2*th), (float)sin(2*th));
        g_twB[2*i+1] = make_float4((float)cos(3*th), (float)sin(3*th), (float)cos(4*th), (float)sin(4*th));
    }
    if (i < 40) {
        double th = -6.283185307179586476925287 * (double)i / 200.0;
        g_twC1[2*i]   = make_float4((float)cos(th),   (float)sin(th),   (float)cos(2*th), (float)sin(2*th));
        g_twC1[2*i+1] = make_float4((float)cos(3*th), (float)sin(3*th), (float)cos(4*th), (float)sin(4*th));
    }
    if (i < 200) {
        double th = -6.283185307179586476925287 * (double)i / 1000.0;
        g_twC2[2*i]   = make_float4((float)cos(th),   (float)sin(th),   (float)cos(2*th), (float)sin(2*th));
        g_twC2[2*i+1] = make_float4((float)cos(3*th), (float)sin(3*th), (float)cos(4*th), (float)sin(4*th));
    }
}

// ---------------- spectrogram: one block per (b, t) frame ----------------
// 1000-pt real DFT, 4-stage factorization: n = 125u + 25v + q, q = 5a + b5
__global__ void __launch_bounds__(128) k_spec(const float* __restrict__ x) {
    const int bid = blockIdx.x;
    const int b = bid / T_, t = bid % T_;
    const float* xin = x + (size_t)b * L_ + (size_t)t * STEP_;

    // shared overlay: xw/Z dead after stage B -> reused by W
    __shared__ __align__(16) char sbuf[13200];
    float* xw  = (float*)sbuf;              // [0, 4000)        1000 floats
    float* Zr  = (float*)(sbuf + 4000);     // [4000, 6500)     5*125
    float* Zi  = (float*)(sbuf + 6500);     // [6500, 9000)     5*125
    float* Yr  = (float*)(sbuf + 9000);     // [9000, 11100)    21*25
    float* Yi  = (float*)(sbuf + 11100);    // [11100, 13200)   21*25
    float* Wr  = (float*)sbuf;              // [0, 4000)        5*200 (over xw)
    float* Wi  = (float*)(sbuf + 4000);     // [4000, 8000)     5*200 (over Z)
    __shared__ float red[4];

    const int tid = threadIdx.x;

    // ---- load frame + detrend mean ----
    float v[8];
    float s = 0.f;
#pragma unroll
    for (int i = 0; i < 8; ++i) {
        int idx = tid + i * 128;
        float vv = 0.f;
        if (i < 7 || tid < 104) vv = xin[idx];
        v[i] = vv; s += vv;
    }
#pragma unroll
    for (int o = 16; o; o >>= 1) s += __shfl_down_sync(0xffffffffu, s, o);
    if ((tid & 31) == 0) red[tid >> 5] = s;
    __syncthreads();
    if (tid == 0) red[0] = (red[0] + red[1] + red[2] + red[3]) * (1.f / 1000.f);
    __syncthreads();
    const float mean = red[0];

    // ---- detrend + Hann window (table) ----
#pragma unroll
    for (int i = 0; i < 8; ++i) {
        int idx = tid + i * 128;
        if (i < 7 || tid < 104)
            xw[idx] = (v[i] - mean) * __ldg(&g_win[idx]);
    }
    __syncthreads();

    // ---- Stage A: 125 real 8-point DFTs (thread tid = 25v + q) ----
    if (tid < 125) {
        float e0 = xw[tid],       e1 = xw[125 + tid], e2 = xw[250 + tid], e3 = xw[375 + tid];
        float e4 = xw[500 + tid], e5 = xw[625 + tid], e6 = xw[750 + tid], e7 = xw[875 + tid];
        float a0 = e0 + e4, a1 = e1 + e5, a2 = e2 + e6, a3 = e3 + e7;
        float b0 = e0 - e4, b1 = e1 - e5, b2 = e2 - e6, b3 = e3 - e7;
        float s1 = a0 + a2, s2 = a1 + a3;
        const float RC = 0.70710678118654752f;
        float t1c = RC * (b1 - b3);
        float t2c = RC * (b1 + b3);
        Zr[0*125 + tid] = s1 + s2;   Zi[0*125 + tid] = 0.f;
        Zr[1*125 + tid] = b0 + t1c;  Zi[1*125 + tid] = -(t2c + b2);
        Zr[2*125 + tid] = a0 - a2;   Zi[2*125 + tid] = -(a1 - a3);
        Zr[3*125 + tid] = b0 - t1c;  Zi[3*125 + tid] = b2 - t2c;
        Zr[4*125 + tid] = s1 - s2;   Zi[4*125 + tid] = 0.f;
    }
    __syncthreads();

    // ---- Stage B: Y[r][q], r = 0..20; threads (r, 5-q chunk) ----
    if (tid < 105) {
        const int r  = tid % 21;
        const int q0 = (tid / 21) * 5;
        float4 ta = __ldg(&g_twB[2*r]), tb = __ldg(&g_twB[2*r + 1]);
        float w1r = ta.x, w1i = ta.y, w2r = ta.z, w2i = ta.w;
        float w3r = tb.x, w3i = tb.y, w4r = tb.z, w4i = tb.w;
        int j = r & 7;
        int jj; float zsg;
        if (j <= 4) { jj = j;     zsg =  1.f; }
        else        { jj = 8 - j; zsg = -1.f; }
        const float* zrb = Zr + jj * 125;
        const float* zib = Zi + jj * 125;
#pragma unroll
        for (int dq = 0; dq < 5; ++dq) {
            int q = q0 + dq;
            float z0r = zrb[q],        z0i = zsg * zib[q];
            float z1r = zrb[25 + q],   z1i = zsg * zib[25 + q];
            float z2r = zrb[50 + q],   z2i = zsg * zib[50 + q];
            float z3r = zrb[75 + q],   z3i = zsg * zib[75 + q];
            float z4r = zrb[100 + q],  z4i = zsg * zib[100 + q];
            float ar = z0r, ai = z0i;
            ar += w1r * z1r - w1i * z1i;  ai += w1r * z1i + w1i * z1r;
            ar += w2r * z2r - w2i * z2i;  ai += w2r * z2i + w2i * z2r;
            ar += w3r * z3r - w3i * z3i;  ai += w3r * z3i + w3i * z3r;
            ar += w4r * z4r - w4i * z4i;  ai += w4r * z4i + w4i * z4r;
            Yr[r*25 + q] = ar; Yi[r*25 + q] = ai;
        }
    }
    __syncthreads();

    const float C1 = 0.30901699437494745f, C2 = -0.80901699437494745f;
    const float S1 = 0.95105651629515357f, S2 =  0.58778525229247313f;

    // ---- Stage C1: radix-5 over a; items (b5, r), r = 0..39 ----
    for (int it = tid; it < 200; it += 128) {
        const int b5 = it / 40, r = it % 40;
        int rr; float ysg;
        if (r <= 20) { rr = r;      ysg =  1.f; }
        else         { rr = 40 - r; ysg = -1.f; }
        float4 ta = __ldg(&g_twC1[2*r]), tb = __ldg(&g_twC1[2*r + 1]);
        float w1r = ta.x, w1i = ta.y, w2r = ta.z, w2i = ta.w;
        float w3r = tb.x, w3i = tb.y, w4r = tb.z, w4i = tb.w;

        const float* yrb = Yr + rr * 25;
        const float* yib = Yi + rr * 25;
        float y0r = yrb[b5],       y0i = ysg * yib[b5];
        float p1r = yrb[5  + b5],  p1i = ysg * yib[5  + b5];
        float p2r = yrb[10 + b5],  p2i = ysg * yib[10 + b5];
        float p3r = yrb[15 + b5],  p3i = ysg * yib[15 + b5];
        float p4r = yrb[20 + b5],  p4i = ysg * yib[20 + b5];

        float y1r = w1r * p1r - w1i * p1i, y1i = w1r * p1i + w1i * p1r;
        float y2r = w2r * p2r - w2i * p2i, y2i = w2r * p2i + w2i * p2r;
        float y3r = w3r * p3r - w3i * p3i, y3i = w3r * p3i + w3i * p3r;
        float y4r = w4r * p4r - w4i * p4i, y4i = w4r * p4i + w4i * p4r;

        float t1r = y1r + y4r, t1i = y1i + y4i;
        float t2r = y2r + y3r, t2i = y2i + y3i;
        float t3r = y1r - y4r, t3i = y1i - y4i;
        float t4r = y2r - y3r, t4i = y2i - y3i;
        float Ar = C1 * t1r + C2 * t2r, Ai = C1 * t1i + C2 * t2i;
        float Br = C2 * t1r + C1 * t2r, Bi = C2 * t1i + C1 * t2i;
        float Cr = S1 * t3r + S2 * t4r, Ci = S1 * t3i + S2 * t4i;
        float Dr = S2 * t3r - S1 * t4r, Di = S2 * t3i - S1 * t4i;

        Wr[b5*200 + r]       = y0r + t1r + t2r;  Wi[b5*200 + r]       = y0i + t1i + t2i;
        Wr[b5*200 + r + 40]  = y0r + Ar + Ci;    Wi[b5*200 + r + 40]  = y0i + Ai - Cr;
        Wr[b5*200 + r + 80]  = y0r + Br + Di;    Wi[b5*200 + r + 80]  = y0i + Bi - Dr;
        Wr[b5*200 + r + 120] = y0r + Br - Di;    Wi[b5*200 + r + 120] = y0i + Bi + Dr;
        Wr[b5*200 + r + 160] = y0r + Ar - Ci;    Wi[b5*200 + r + 160] = y0i + Ai + Cr;
    }
    __syncthreads();

    // ---- Stage C2: twiddle + partial DFT-5 (c = 0,1,2) + psd/log ----
    float* outrow = g_tmp + ((size_t)b * T_ + t) * KP_;
    const float SC2 = 2.f / 46875.f;  // fs * sum(win^2) = 125 * 375
    for (int m = tid; m < 200; m += 128) {
        float4 ta = __ldg(&g_twC2[2*m]), tb = __ldg(&g_twC2[2*m + 1]);
        float w1r = ta.x, w1i = ta.y, w2r = ta.z, w2i = ta.w;
        float w3r = tb.x, w3i = tb.y, w4r = tb.z, w4i = tb.w;

        float z0r = Wr[m],        z0i = Wi[m];
        float p1r = Wr[200 + m],  p1i = Wi[200 + m];
        float p2r = Wr[400 + m],  p2i = Wi[400 + m];
        float p3r = Wr[600 + m],  p3i = Wi[600 + m];
        float p4r = Wr[800 + m],  p4i = Wi[800 + m];

        float z1r = w1r * p1r - w1i * p1i, z1i = w1r * p1i + w1i * p1r;
        float z2r = w2r * p2r - w2i * p2i, z2i = w2r * p2i + w2i * p2r;
        float z3r = w3r * p3r - w3i * p3i, z3i = w3r * p3i + w3i * p3r;
        float z4r = w4r * p4r - w4i * p4i, z4i = w4r * p4i + w4i * p4r;

        float t1r = z1r + z4r, t1i = z1i + z4i;
        float t2r = z2r + z3r, t2i = z2i + z3i;
        float t3r = z1r - z4r, t3i = z1i - z4i;
        float t4r = z2r - z3r, t4i = z2i - z3i;

        {   // c = 0 : k = m
            float Xr = z0r + t1r + t2r, Xi = z0i + t1i + t2i;
            float sc = (m == 0) ? (1.f / 46875.f) : SC2;
            outrow[m] = __logf((Xr * Xr + Xi * Xi) * sc + 1e-8f);
        }
        float Ar = C1 * t1r + C2 * t2r, Ai = C1 * t1i + C2 * t2i;
        float Cr = S1 * t3r + S2 * t4r, Ci = S1 * t3i + S2 * t4i;
        {   // c = 1 : k = m + 200
            float Xr = z0r + Ar + Ci, Xi = z0i + Ai - Cr;
            outrow[m + 200] = __logf((Xr * Xr + Xi * Xi) * SC2 + 1e-8f);
        }
        if (m <= 100) {  // c = 2 : k = m + 400
            float Br = C2 * t1r + C1 * t2r, Bi = C2 * t1i + C1 * t2i;
            float Dr = S2 * t3r - S1 * t4r, Di = S2 * t3i - S1 * t4i;
            float Xr = z0r + Br + Di, Xi = z0i + Bi - Dr;
            float sc = (m == 100) ? (1.f / 46875.f) : SC2;
            outrow[m + 400] = __logf((Xr * Xr + Xi * Xi) * sc + 1e-8f);
        }
    }
}

// ---------------- transpose [b][t][k] -> spec[b][k][t]; fused env + mel ----------------
__global__ void __launch_bounds__(256) k_transpose(float* __restrict__ spec,
                                                   float* __restrict__ mel) {
    const int bb = blockIdx.x >> 4;
    const int k0 = (blockIdx.x & 15) * 32;
    const int tid = threadIdx.x;
    __shared__ float tile[T_][33];

    for (int i = tid; i < T_ * 32; i += 256) {
        int tt = i >> 5, kx = i & 31;
        int k = k0 + kx;
        tile[tt][kx] = (k < NF_) ? g_tmp[((size_t)bb * T_ + tt) * KP_ + k] : 0.f;
    }
    __syncthreads();

    for (int i = tid; i < 32 * T_; i += 256) {
        int kx = i / T_, tt = i - kx * T_;
        int k = k0 + kx;
        if (k < NF_) spec[((size_t)bb * NF_ + k) * T_ + tt] = tile[tt][kx];
    }
    if (tid < 32) {
        int k = k0 + tid;
        if (k < NF_) {
            float s = 0.f;
            for (int tt = 0; tt < T_; ++tt) s += tile[tt][tid];
            g_env[bb * NF_ + k] = s * (1.f / (float)T_);
        }
    }
    // mel gather: all centers are in [0, 25) -> handled by the k0 == 0 tile
    if (k0 == 0) {
        for (int i = tid; i < NMEL_ * T_; i += 256) {
            int m = i / T_, tt = i - m * T_;
            int c = g_centers[m];
            mel[(size_t)bb * NMEL_ * T_ + i] = (c >= 0) ? tile[tt][c] : 0.f;
        }
    }
}

// ---------------- BN stats: conv sums (PASS=0) / var sums (PASS=1) ----------------
template<int PASS>
__global__ void __launch_bounds__(256) k_bnstats(const float* __restrict__ w5, const float* __restrict__ b5,
                                                 const float* __restrict__ w7, const float* __restrict__ b7) {
    const int b = blockIdx.x, tid = threadIdx.x;
    __shared__ float e[NF_ + 4];
    __shared__ float cp[24];
    for (int i = tid; i < NF_ + 4; i += 256) {
        int f = i - 2;
        e[i] = (f >= 0 && f < NF_) ? g_env[b * NF_ + f] : 0.f;
    }
    if (tid < 24) {
        int j = tid - 3;
        cp[tid] = (j >= 0 && j < 18) ? g_env[b * NF_ + 6 + j] : 0.f;
    }
    __syncthreads();

    {
        const int o = tid >> 3, sub = tid & 7;
        float wv[5];
#pragma unroll
        for (int k = 0; k < 5; ++k) wv[k] = w5[o * 5 + k];
        const float bb = b5[o];
        const float m  = PASS ? g_meanS[o] : 0.f;
        float acc = 0.f;
        for (int l = sub; l < NF_; l += 8) {
            float y = bb;
#pragma unroll
            for (int k = 0; k < 5; ++k) y += wv[k] * e[l + k];
            if (PASS) { float d = y - m; acc += d * d; } else acc += y;
        }
#pragma unroll
        for (int d = 4; d; d >>= 1) acc += __shfl_down_sync(0xffffffffu, acc, d, 8);
        if (sub == 0) g_psumS[b * 32 + o] = acc;
    }
    if (tid < 24) {
        const int oc = tid;
        const float m = PASS ? g_meanC[oc] : 0.f;
        float acc = 0.f;
        for (int l = 0; l < 18; ++l) {
            float y = b7[oc];
#pragma unroll
            for (int k = 0; k < 7; ++k) y += w7[oc * 7 + k] * cp[l + k];
            if (PASS) { float d = y - m; acc += d * d; } else acc += y;
        }
        g_psumC[b * 24 + oc] = acc;
    }
}

__global__ void k_reduce_mean() {
    int t = threadIdx.x;
    if (t < 32) {
        float s = 0.f;
        for (int b = 0; b < B_; ++b) s += g_psumS[b * 32 + t];
        g_meanS[t] = s / (float)(B_ * NF_);
    } else if (t < 56) {
        int o = t - 32; float s = 0.f;
        for (int b = 0; b < B_; ++b) s += g_psumC[b * 24 + o];
        g_meanC[o] = s / (float)(B_ * 18);
    }
}

__global__ void k_reduce_var(const float* __restrict__ gS, const float* __restrict__ btS,
                             const float* __restrict__ gC, const float* __restrict__ btC) {
    int t = threadIdx.x;
    if (t < 32) {
        float s = 0.f;
        for (int b = 0; b < B_; ++b) s += g_psumS[b * 32 + t];
        float var = s / (float)(B_ * NF_);
        float a = gS[t] * rsqrtf(var + 1e-5f);
        g_aS[t] = a; g_cS[t] = btS[t] - g_meanS[t] * a;
    } else if (t < 56) {
        int o = t - 32; float s = 0.f;
        for (int b = 0; b < B_; ++b) s += g_psumC[b * 24 + o];
        float var = s / (float)(B_ * 18);
        float a = gC[o] * rsqrtf(var + 1e-5f);
        g_aC[o] = a; g_cC[o] = btC[o] - g_meanC[o] * a;
    }
}

// ---------------- finalize: spectral out, cfeat, rfeat ----------------
__global__ void __launch_bounds__(256) k_final(const float* __restrict__ w5, const float* __restrict__ b5,
                                               const float* __restrict__ w7, const float* __restrict__ b7,
                                               const float* __restrict__ w1, const float* __restrict__ b1,
                                               const float* __restrict__ w2, const float* __restrict__ b2,
                                               float* __restrict__ outSpectral,
                                               float* __restrict__ outR,
                                               float* __restrict__ outC) {
    const int b = blockIdx.x, tid = threadIdx.x;
    __shared__ float e[NF_ + 4];
    __shared__ float cp[24];
    __shared__ float ws5[160], bs5[32], aSs[32], cSs[32];
    __shared__ float rpp[9];
    __shared__ float r1p[16][7];

    for (int i = tid; i < NF_ + 4; i += 256) {
        int f = i - 2;
        e[i] = (f >= 0 && f < NF_) ? g_env[b * NF_ + f] : 0.f;
    }
    if (tid < 24) {
        int j = tid - 3;
        cp[tid] = (j >= 0 && j < 18) ? g_env[b * NF_ + 6 + j] : 0.f;
    }
    if (tid < 160) ws5[tid] = w5[tid];
    if (tid < 32) { bs5[tid] = b5[tid]; aSs[tid] = g_aS[tid]; cSs[tid] = g_cS[tid]; }
    if (tid < 9) {
        int j = tid - 2;
        rpp[tid] = (j >= 0 && j < 4) ? g_env[b * NF_ + j] : 0.f;
    }
    if (tid < 16) { r1p[tid][0] = 0.f; r1p[tid][6] = 0.f; }
    __syncthreads();

    if (tid < 80) {
        int i = tid / 5, l = tid % 5;
        float y = b1[i];
#pragma unroll
        for (int k = 0; k < 5; ++k) y += w1[i * 5 + k] * rpp[l + k];
        r1p[i][l + 1] = fmaxf(0.f, y);
    }

    for (int idx = tid; idx < 32 * NF_; idx += 256) {
        int o = idx / NF_, l = idx - o * NF_;
        float y = bs5[o];
#pragma unroll
        for (int k = 0; k < 5; ++k) y += ws5[o * 5 + k] * e[l + k];
        outSpectral[(size_t)b * 32 * NF_ + idx] = fmaxf(0.f, y * aSs[o] + cSs[o]);
    }

    if (tid < 32) {
        float val = 0.f;
        if (tid < 24) {
            const int oc = tid;
            const float a = g_aC[oc], c = g_cC[oc];
            float acc = 0.f;
            for (int l = 0; l < 18; ++l) {
                float y = b7[oc];
#pragma unroll
                for (int k = 0; k < 7; ++k) y += w7[oc * 7 + k] * cp[l + k];
                acc += fmaxf(0.f, y * a + c);
            }
            val = acc / 18.f;
        }
        outC[b * 32 + tid] = val;
    }
    __syncthreads();

    if (tid < 32) {
        const int o = tid;
        float acc = 5.f * b2[o];
        for (int i = 0; i < 16; ++i) {
#pragma unroll
            for (int l = 0; l < 5; ++l)
#pragma unroll
                for (int k = 0; k < 3; ++k)
                    acc += w2[o * 48 + i * 3 + k] * r1p[i][l + k];
        }
        outR[b * 32 + o] = acc * 0.2f;
    }
}

// ---------------- launch ----------------
extern "C" void kernel_launch(void* const* d_in, const int* in_sizes, int n_in,
                              void* d_out, int out_size) {
    (void)in_sizes; (void)n_in; (void)out_size;
    const float* x   = (const float*)d_in[0];
    const float* w5  = (const float*)d_in[1];
    const float* b5  = (const float*)d_in[2];
    const float* g5  = (const float*)d_in[3];
    const float* bt5 = (const float*)d_in[4];
    const float* w7  = (const float*)d_in[5];
    const float* b7  = (const float*)d_in[6];
    const float* g7  = (const float*)d_in[7];
    const float* bt7 = (const float*)d_in[8];
    const float* w1  = (const float*)d_in[9];
    const float* b1  = (const float*)d_in[10];
    const float* w2  = (const float*)d_in[11];
    const float* b2  = (const float*)d_in[12];

    float* out         = (float*)d_out;
    float* outMel      = out;
    float* outSpectral = outMel + (size_t)B_ * 64 * T_;
    float* outR        = outSpectral + (size_t)B_ * 32 * NF_;
    float* outC        = outR + (size_t)B_ * 32;
    float* outSpec     = outC + (size_t)B_ * 32;

    k_init<<<8, 128>>>();
    k_spec<<<B_ * T_, 128>>>(x);
    k_transpose<<<B_ * 16, 256>>>(outSpec, outMel);
    k_bnstats<0><<<B_, 256>>>(w5, b5, w7, b7);
    k_reduce_mean<<<1, 64>>>();
    k_bnstats<1><<<B_, 256>>>(w5, b5, w7, b7);
    k_reduce_var<<<1, 64>>>(g5, bt5, g7, bt7);
    k_final<<<B_, 256>>>(w5, b5, w7, b7, w1, b1, w2, b2, outSpectral, outR, outC);
}